// round 5
// baseline (speedup 1.0000x reference)
#include <cuda_runtime.h>
#include <cuda.h>
#include <math.h>
#include <stdint.h>

// ---------------- problem constants ----------------
#define NT      16384
#define DIM     2048
#define NE      64
#define TOPK    8
#define TILE_M  64
#define KC      64
#define NCHUNK  (DIM / KC)     // 32
#define THREADS 256

// ---------------- smem layout ----------------
#define X_STAGE  16384          // 64 tok x 64 k fp32 (two 8KB SW128 subtiles)
#define W_STAGE  16384          // 32 kpair x 64 experts x float2
#define OFF_MBAR 0
#define OFF_GB   64
#define OFF_X    1024
#define OFF_W    (OFF_X + 2 * X_STAGE)      // 33792
#define SMEM_TOTAL (OFF_W + 2 * W_STAGE)    // 66560
#define TX_BYTES (X_STAGE + W_STAGE)

// interleaved weights: g_wp[kp][e][2] = { w[e][2kp], w[e][2kp+1] }
__device__ __align__(1024) float g_wp[(DIM / 2) * NE * 2];
__device__ int g_nflag;
__device__ int g_flags[8192];

// ---------------- helpers ----------------
__device__ __forceinline__ uint32_t smem_u32(const void* p) {
    uint32_t a;
    asm("{ .reg .u64 t; cvta.to.shared.u64 t, %1; cvt.u32.u64 %0, t; }" : "=r"(a) : "l"(p));
    return a;
}

#define MBAR_INIT(addr, cnt) \
    asm volatile("mbarrier.init.shared.b64 [%0], %1;" :: "r"(addr), "r"((uint32_t)(cnt)) : "memory")
#define MBAR_EXPECT_TX(addr, bytes) \
    asm volatile("mbarrier.arrive.expect_tx.shared.b64 _, [%0], %1;" :: "r"(addr), "r"((uint32_t)(bytes)) : "memory")

#define MBAR_WAIT(addr, parity) do {                                           \
    uint32_t _m = (addr); uint32_t _p = (parity); uint32_t _d;                 \
    asm volatile("{\n\t.reg .pred p;\n\t"                                      \
        "mbarrier.try_wait.parity.acquire.cta.shared::cta.b64 p, [%1], %2;\n\t"\
        "selp.b32 %0, 1, 0, p;\n\t}"                                           \
        : "=r"(_d) : "r"(_m), "r"(_p) : "memory");                             \
    if (!_d) {                                                                 \
        asm volatile("{\n\t.reg .pred P1;\n\t"                                 \
            "WL_%=:\n\t"                                                       \
            "mbarrier.try_wait.parity.acquire.cta.shared::cta.b64 P1, [%0], %1, 0x989680;\n\t" \
            "@P1 bra.uni WD_%=;\n\t"                                           \
            "bra.uni WL_%=;\n\t"                                               \
            "WD_%=:\n\t}" :: "r"(_m), "r"(_p) : "memory");                     \
    }                                                                          \
} while (0)

__device__ __forceinline__ void tma_2d(uint32_t dst, const CUtensorMap* map,
                                       int32_t cx, int32_t cy, uint32_t mbar) {
    asm volatile(
        "cp.async.bulk.tensor.2d.shared::cta.global.tile.mbarrier::complete_tx::bytes "
        "[%0], [%1, {%2, %3}], [%4];"
        :: "r"(dst), "l"(map), "r"(cx), "r"(cy), "r"(mbar) : "memory");
}

// packed dual-fp32 FMA: acc.{lo,hi} += a.{lo,hi} * b.{lo,hi}
#define FFMA2(acc, a, b) \
    asm("fma.rn.f32x2 %0, %1, %2, %0;" : "+l"(acc) : "l"(a), "l"(b))

#define LDS64(v, addr) \
    asm volatile("ld.shared.b64 %0, [%1];" : "=l"(v) : "r"(addr))
#define LDS128_U64(v0, v1, addr) \
    asm volatile("ld.shared.v2.u64 {%0, %1}, [%2];" : "=l"(v0), "=l"(v1) : "r"(addr))

// ---------------- prep: interleave w into [kp][e][2]; reset flags ----------------
__global__ void prep_kernel(const float* __restrict__ w) {
    int idx = blockIdx.x * 256 + threadIdx.x;      // 0 .. 131071
    if (idx == 0) g_nflag = 0;
    int kp = idx >> 7;
    int r  = idx & 127;
    int e  = r >> 1;
    int j  = r & 1;
    g_wp[idx] = w[e * DIM + 2 * kp + j];
}

// ---------------- main gate kernel ----------------
__global__ __launch_bounds__(THREADS) void gate_kernel(
    const __grid_constant__ CUtensorMap tmx,
    const __grid_constant__ CUtensorMap tmw,
    const float* __restrict__ gate_b,
    float* __restrict__ out)
{
    extern __shared__ __align__(1024) char smem[];
    const uint32_t sb = smem_u32(smem);
    const int tid = threadIdx.x;
    const int lane = tid & 31;
    const int wid = tid >> 5;
    const int tok0 = blockIdx.x * TILE_M;

    if (tid == 0) {
        MBAR_INIT(sb + OFF_MBAR + 0, 1);
        MBAR_INIT(sb + OFF_MBAR + 8, 1);
    }
    if (tid < NE) ((float*)(smem + OFF_GB))[tid] = gate_b[tid];
    __syncthreads();

    if (tid == 0) {
#pragma unroll
        for (int s = 0; s < 2; s++) {
            MBAR_EXPECT_TX(sb + OFF_MBAR + s * 8, TX_BYTES);
            tma_2d(sb + OFF_X + s * X_STAGE, &tmx, s * KC, tok0, sb + OFF_MBAR + s * 8);
            tma_2d(sb + OFF_X + s * X_STAGE + 8192, &tmx, s * KC + 32, tok0, sb + OFF_MBAR + s * 8);
            tma_2d(sb + OFF_W + s * W_STAGE, &tmw, 0, s * 32, sb + OFF_MBAR + s * 8);
        }
    }

    // warp handles experts [wid*8, wid*8+8); lane handles tokens lane, lane+32
    unsigned long long acc[2][8];
#pragma unroll
    for (int i = 0; i < 2; i++)
#pragma unroll
        for (int u = 0; u < 8; u++) acc[i][u] = 0ULL;

    const uint32_t e8 = (uint32_t)wid * 64;
    const uint32_t xsw = ((uint32_t)(lane & 7)) << 4;
    const uint32_t trow = (uint32_t)lane * 128;

    for (int c = 0; c < NCHUNK; c++) {
        const int s = c & 1, ph = (c >> 1) & 1;
        MBAR_WAIT(sb + OFF_MBAR + s * 8, ph);

        const uint32_t xb = sb + OFF_X + s * X_STAGE;
        const uint32_t wb = sb + OFF_W + s * W_STAGE + e8;

#pragma unroll 4
        for (int kp = 0; kp < 32; kp++) {
            const uint32_t cc = (uint32_t)(kp & 15) * 8;
            const uint32_t arow = xb + ((kp >> 4) * 8192) + ((cc & 0x70u) ^ xsw) + (cc & 8u) + trow;
            unsigned long long a0, a1;
            LDS64(a0, arow);
            LDS64(a1, arow + 4096);

            const uint32_t wrow = wb + (uint32_t)kp * 512;
            unsigned long long b0, b1, b2, b3, b4, b5, b6, b7;
            LDS128_U64(b0, b1, wrow);
            LDS128_U64(b2, b3, wrow + 16);
            LDS128_U64(b4, b5, wrow + 32);
            LDS128_U64(b6, b7, wrow + 48);

            FFMA2(acc[0][0], a0, b0); FFMA2(acc[0][1], a0, b1);
            FFMA2(acc[0][2], a0, b2); FFMA2(acc[0][3], a0, b3);
            FFMA2(acc[0][4], a0, b4); FFMA2(acc[0][5], a0, b5);
            FFMA2(acc[0][6], a0, b6); FFMA2(acc[0][7], a0, b7);
            FFMA2(acc[1][0], a1, b0); FFMA2(acc[1][1], a1, b1);
            FFMA2(acc[1][2], a1, b2); FFMA2(acc[1][3], a1, b3);
            FFMA2(acc[1][4], a1, b4); FFMA2(acc[1][5], a1, b5);
            FFMA2(acc[1][6], a1, b6); FFMA2(acc[1][7], a1, b7);
        }
        __syncthreads();

        if (tid == 0 && c + 2 < NCHUNK) {
            MBAR_EXPECT_TX(sb + OFF_MBAR + s * 8, TX_BYTES);
            tma_2d(sb + OFF_X + s * X_STAGE, &tmx, (c + 2) * KC, tok0, sb + OFF_MBAR + s * 8);
            tma_2d(sb + OFF_X + s * X_STAGE + 8192, &tmx, (c + 2) * KC + 32, tok0, sb + OFF_MBAR + s * 8);
            tma_2d(sb + OFF_W + s * W_STAGE, &tmw, 0, (c + 2) * 32, sb + OFF_MBAR + s * 8);
        }
    }

    // ---- epilogue ----
    float* sc = (float*)(smem + OFF_X);   // [64 tok][67]
    {
        const int e0 = wid * 8;
#pragma unroll
        for (int u = 0; u < 8; u++) {
            float lo, hi;
            asm("mov.b64 {%0, %1}, %2;" : "=f"(lo), "=f"(hi) : "l"(acc[0][u]));
            sc[lane * 67 + e0 + u] = lo + hi;
            asm("mov.b64 {%0, %1}, %2;" : "=f"(lo), "=f"(hi) : "l"(acc[1][u]));
            sc[(lane + 32) * 67 + e0 + u] = lo + hi;
        }
    }
    __syncthreads();

    if (tid < TILE_M) {
        const long token = tok0 + tid;
        const float* gb = (const float*)(smem + OFF_GB);
        float s[NE];
#pragma unroll
        for (int e = 0; e < NE; e++)
            s[e] = 1.f / (1.f + expf(-sc[tid * 67 + e])) + gb[e];

        float* so = out + 2L * NT * TOPK + token * NE;
#pragma unroll
        for (int i = 0; i < 16; i++)
            *(float4*)&so[4 * i] = make_float4(s[4 * i], s[4 * i + 1], s[4 * i + 2], s[4 * i + 3]);

        // top-8, strict > keeps lowest index on ties (matches jax top_k)
        unsigned m0 = 0, m1 = 0;
        float wk[TOPK];
        int ik[TOPK];
        float sum = 0.f;
#pragma unroll 1
        for (int k = 0; k < TOPK; k++) {
            float best = -1e30f;
            int bi = 0;
#pragma unroll
            for (int e = 0; e < NE; e++) {
                unsigned bit = (e < 32) ? (m0 >> e) : (m1 >> (e - 32));
                if (((bit & 1u) == 0u) && (s[e] > best)) { best = s[e]; bi = e; }
            }
            if (bi < 32) m0 |= (1u << bi); else m1 |= (1u << (bi - 32));
            wk[k] = best; ik[k] = bi; sum += best;
        }
        // near-tie detection (incl. rank-8/9 boundary) -> flag for exact refine
        float v9 = -1e30f;
#pragma unroll
        for (int e = 0; e < NE; e++) {
            unsigned bit = (e < 32) ? (m0 >> e) : (m1 >> (e - 32));
            if (((bit & 1u) == 0u) && (s[e] > v9)) v9 = s[e];
        }
        float mingap = wk[TOPK - 1] - v9;
#pragma unroll
        for (int k = 0; k < TOPK - 1; k++) {
            float gdiff = wk[k] - wk[k + 1];
            if (gdiff < mingap) mingap = gdiff;
        }
        if (mingap < 2e-5f) {
            int ix = atomicAdd(&g_nflag, 1);
            if (ix < 8192) g_flags[ix] = (int)token;
        }

        float inv = 1.f / sum;
        *(float4*)&out[token * TOPK] = make_float4(wk[0] * inv, wk[1] * inv, wk[2] * inv, wk[3] * inv);
        *(float4*)&out[token * TOPK + 4] = make_float4(wk[4] * inv, wk[5] * inv, wk[6] * inv, wk[7] * inv);
        *(float4*)&out[NT * TOPK + token * TOPK] = make_float4((float)ik[0], (float)ik[1], (float)ik[2], (float)ik[3]);
        *(float4*)&out[NT * TOPK + token * TOPK + 4] = make_float4((float)ik[4], (float)ik[5], (float)ik[6], (float)ik[7]);
    }
}

// ---------------- refine: exact fp32 recompute for near-tie tokens ----------------
// (identical summation order to the R3 kernel that passed on this seed)
__global__ void refine_kernel(const float* __restrict__ x,
                              const float* __restrict__ w,
                              const float* __restrict__ gate_b,
                              float* __restrict__ out)
{
    __shared__ float xs[DIM];
    __shared__ float part[NE][4];
    __shared__ float sc[NE];
    int n = g_nflag;
    if (n > 8192) n = 8192;
    for (int i = blockIdx.x; i < n; i += gridDim.x) {
        const int token = g_flags[i];
        __syncthreads();
        for (int d = threadIdx.x; d < DIM; d += 256) xs[d] = x[(long)token * DIM + d];
        __syncthreads();
        {
            const int e = threadIdx.x >> 2, q = threadIdx.x & 3;
            const float* wr = w + (long)e * DIM + q * 512;
            const float* xr = xs + q * 512;
            float s0 = 0.f, s1 = 0.f, s2 = 0.f, s3 = 0.f;
#pragma unroll 8
            for (int d = 0; d < 512; d += 4) {
                s0 = fmaf(xr[d], wr[d], s0);
                s1 = fmaf(xr[d + 1], wr[d + 1], s1);
                s2 = fmaf(xr[d + 2], wr[d + 2], s2);
                s3 = fmaf(xr[d + 3], wr[d + 3], s3);
            }
            part[e][q] = (s0 + s1) + (s2 + s3);
        }
        __syncthreads();
        if (threadIdx.x < NE) {
            float l = (part[threadIdx.x][0] + part[threadIdx.x][1]) +
                      (part[threadIdx.x][2] + part[threadIdx.x][3]);
            float v = 1.f / (1.f + expf(-l)) + gate_b[threadIdx.x];
            sc[threadIdx.x] = v;
            out[2L * NT * TOPK + (long)token * NE + threadIdx.x] = v;
        }
        __syncthreads();
        if (threadIdx.x == 0) {
            unsigned m0 = 0, m1 = 0;
            float wk[TOPK];
            int ik[TOPK];
            float sum = 0.f;
            for (int k = 0; k < TOPK; k++) {
                float best = -1e30f;
                int bi = 0;
                for (int e = 0; e < NE; e++) {
                    unsigned bit = (e < 32) ? (m0 >> e) : (m1 >> (e - 32));
                    if (((bit & 1u) == 0u) && (sc[e] > best)) { best = sc[e]; bi = e; }
                }
                if (bi < 32) m0 |= (1u << bi); else m1 |= (1u << (bi - 32));
                wk[k] = best; ik[k] = bi; sum += best;
            }
            float inv = 1.f / sum;
            for (int k = 0; k < TOPK; k++) {
                out[(long)token * TOPK + k] = wk[k] * inv;
                out[NT * TOPK + (long)token * TOPK + k] = (float)ik[k];
            }
        }
    }
}

// ---------------- host ----------------
typedef CUresult (*EncodeFn)(CUtensorMap*, CUtensorMapDataType, cuuint32_t, void*,
                             const cuuint64_t*, const cuuint64_t*, const cuuint32_t*,
                             const cuuint32_t*, CUtensorMapInterleave, CUtensorMapSwizzle,
                             CUtensorMapL2promotion, CUtensorMapFloatOOBfill);

static EncodeFn get_encode_fn() {
    static EncodeFn fn = nullptr;
    if (!fn) {
        void* p = nullptr;
        cudaDriverEntryPointQueryResult qr;
        cudaGetDriverEntryPoint("cuTensorMapEncodeTiled", &p, cudaEnableDefault, &qr);
        fn = (EncodeFn)p;
    }
    return fn;
}

extern "C" void kernel_launch(void* const* d_in, const int* in_sizes, int n_in,
                              void* d_out, int out_size) {
    const float* x  = (const float*)d_in[0];
    const float* w  = (const float*)d_in[1];
    const float* gb = (const float*)d_in[2];
    float* out = (float*)d_out;

    prep_kernel<<<(DIM / 2) * NE * 2 / 256, 256>>>(w);

    void* wpp = nullptr;
    cudaGetSymbolAddress(&wpp, g_wp);

    EncodeFn enc = get_encode_fn();
    CUtensorMap tmx, tmw;
    {
        cuuint64_t dims[2]    = {DIM, NT};
        cuuint64_t strides[1] = {DIM * sizeof(float)};
        cuuint32_t box[2]     = {32, TILE_M};
        cuuint32_t es[2]      = {1, 1};
        enc(&tmx, CU_TENSOR_MAP_DATA_TYPE_FLOAT32, 2, (void*)x,
            dims, strides, box, es,
            CU_TENSOR_MAP_INTERLEAVE_NONE, CU_TENSOR_MAP_SWIZZLE_128B,
            CU_TENSOR_MAP_L2_PROMOTION_L2_128B, CU_TENSOR_MAP_FLOAT_OOB_FILL_NONE);
    }
    {
        cuuint64_t dims[2]    = {2 * NE, DIM / 2};
        cuuint64_t strides[1] = {2 * NE * sizeof(float)};
        cuuint32_t box[2]     = {2 * NE, 32};
        cuuint32_t es[2]      = {1, 1};
        enc(&tmw, CU_TENSOR_MAP_DATA_TYPE_FLOAT32, 2, wpp,
            dims, strides, box, es,
            CU_TENSOR_MAP_INTERLEAVE_NONE, CU_TENSOR_MAP_SWIZZLE_NONE,
            CU_TENSOR_MAP_L2_PROMOTION_L2_128B, CU_TENSOR_MAP_FLOAT_OOB_FILL_NONE);
    }

    cudaFuncSetAttribute(gate_kernel, cudaFuncAttributeMaxDynamicSharedMemorySize, SMEM_TOTAL);
    gate_kernel<<<NT / TILE_M, THREADS, SMEM_TOTAL>>>(tmx, tmw, gb, out);
    refine_kernel<<<64, 256>>>(x, w, gb, out);
}

// round 6
// speedup vs baseline: 1.0848x; 1.0848x over previous
#include <cuda_runtime.h>
#include <cuda.h>
#include <math.h>
#include <stdint.h>

// ---------------- problem constants ----------------
#define NT      16384
#define DIM     2048
#define NE      64
#define TOPK    8
#define TILE_M  64
#define KC      64
#define NCHUNK  (DIM / KC)     // 32
#define THREADS 256

// ---------------- smem layout ----------------
#define X_STAGE  16384          // 64 tok x 64 k fp32, rows 256B
#define W_STAGE  16384          // 64 k   x 64 e fp32, rows 256B
#define OFF_MBAR 0
#define OFF_GB   64
#define OFF_X    1024
#define OFF_W    (OFF_X + 2 * X_STAGE)      // 33792
#define SMEM_TOTAL (OFF_W + 2 * W_STAGE)    // 66560
#define TX_BYTES (X_STAGE + W_STAGE)

// transposed router weights: g_wT[d][e] = w[e][d]
__device__ __align__(1024) float g_wT[DIM * NE];
__device__ int g_nflag;
__device__ int g_flags[8192];

// ---------------- helpers ----------------
__device__ __forceinline__ uint32_t smem_u32(const void* p) {
    uint32_t a;
    asm("{ .reg .u64 t; cvta.to.shared.u64 t, %1; cvt.u32.u64 %0, t; }" : "=r"(a) : "l"(p));
    return a;
}

#define MBAR_INIT(addr, cnt) \
    asm volatile("mbarrier.init.shared.b64 [%0], %1;" :: "r"(addr), "r"((uint32_t)(cnt)) : "memory")
#define MBAR_EXPECT_TX(addr, bytes) \
    asm volatile("mbarrier.arrive.expect_tx.shared.b64 _, [%0], %1;" :: "r"(addr), "r"((uint32_t)(bytes)) : "memory")

#define MBAR_WAIT(addr, parity) do {                                           \
    uint32_t _m = (addr); uint32_t _p = (parity); uint32_t _d;                 \
    asm volatile("{\n\t.reg .pred p;\n\t"                                      \
        "mbarrier.try_wait.parity.acquire.cta.shared::cta.b64 p, [%1], %2;\n\t"\
        "selp.b32 %0, 1, 0, p;\n\t}"                                           \
        : "=r"(_d) : "r"(_m), "r"(_p) : "memory");                             \
    if (!_d) {                                                                 \
        asm volatile("{\n\t.reg .pred P1;\n\t"                                 \
            "WL_%=:\n\t"                                                       \
            "mbarrier.try_wait.parity.acquire.cta.shared::cta.b64 P1, [%0], %1, 0x989680;\n\t" \
            "@P1 bra.uni WD_%=;\n\t"                                           \
            "bra.uni WL_%=;\n\t"                                               \
            "WD_%=:\n\t}" :: "r"(_m), "r"(_p) : "memory");                     \
    }                                                                          \
} while (0)

__device__ __forceinline__ void tma_2d(uint32_t dst, const CUtensorMap* map,
                                       int32_t cx, int32_t cy, uint32_t mbar) {
    asm volatile(
        "cp.async.bulk.tensor.2d.shared::cta.global.tile.mbarrier::complete_tx::bytes "
        "[%0], [%1, {%2, %3}], [%4];"
        :: "r"(dst), "l"(map), "r"(cx), "r"(cy), "r"(mbar) : "memory");
}

#define LDS128_F4(v, addr) \
    asm volatile("ld.shared.v4.f32 {%0, %1, %2, %3}, [%4];" \
        : "=f"((v).x), "=f"((v).y), "=f"((v).z), "=f"((v).w) : "r"(addr))

// ---------------- prep: transpose w -> wT[d][e]; reset flags ----------------
__global__ void prep_kernel(const float* __restrict__ w) {
    int idx = blockIdx.x * 256 + threadIdx.x;   // 0 .. DIM*NE-1
    if (idx == 0) g_nflag = 0;
    int d = idx >> 6;
    int e = idx & 63;
    g_wT[idx] = w[e * DIM + d];                 // coalesced write
}

// ---------------- main gate kernel ----------------
__global__ __launch_bounds__(THREADS) void gate_kernel(
    const __grid_constant__ CUtensorMap tmx,
    const __grid_constant__ CUtensorMap tmw,
    const float* __restrict__ gate_b,
    float* __restrict__ out)
{
    extern __shared__ __align__(1024) char smem[];
    const uint32_t sb = smem_u32(smem);
    const int tid = threadIdx.x;
    const int tg = tid >> 4;        // token group 0..15
    const int eg = tid & 15;        // expert group 0..15
    const int tok0 = blockIdx.x * TILE_M;

    if (tid == 0) {
        MBAR_INIT(sb + OFF_MBAR + 0, 1);
        MBAR_INIT(sb + OFF_MBAR + 8, 1);
    }
    if (tid < NE) ((float*)(smem + OFF_GB))[tid] = gate_b[tid];
    __syncthreads();

    if (tid == 0) {
#pragma unroll
        for (int s = 0; s < 2; s++) {
            MBAR_EXPECT_TX(sb + OFF_MBAR + s * 8, TX_BYTES);
            tma_2d(sb + OFF_X + s * X_STAGE, &tmx, s * KC, tok0, sb + OFF_MBAR + s * 8);
            tma_2d(sb + OFF_W + s * W_STAGE, &tmw, 0, s * KC, sb + OFF_MBAR + s * 8);
        }
    }

    float acc[4][4];
#pragma unroll
    for (int i = 0; i < 4; i++)
#pragma unroll
        for (int j = 0; j < 4; j++) acc[i][j] = 0.f;

    const uint32_t abase = (uint32_t)(tg * 4) * 256;   // token rows
    const uint32_t bbase = (uint32_t)eg * 16;          // expert column bytes

    for (int c = 0; c < NCHUNK; c++) {
        const int s = c & 1, ph = (c >> 1) & 1;
        MBAR_WAIT(sb + OFF_MBAR + s * 8, ph);

        const uint32_t xb = sb + OFF_X + s * X_STAGE + abase;
        const uint32_t wb = sb + OFF_W + s * W_STAGE + bbase;

        float4 a[2][4], b[2][4];
        // preload k-step 0
#pragma unroll
        for (int i = 0; i < 4; i++) LDS128_F4(a[0][i], xb + i * 256u);
#pragma unroll
        for (int q = 0; q < 4; q++) LDS128_F4(b[0][q], wb + q * 256u);

#pragma unroll
        for (int kk = 0; kk < 16; kk++) {
            const int cur = kk & 1, nxt = cur ^ 1;
            if (kk < 15) {
                const uint32_t ao = (uint32_t)(kk + 1) * 16;
                const uint32_t bo = (uint32_t)(kk + 1) * 1024;
#pragma unroll
                for (int i = 0; i < 4; i++) LDS128_F4(a[nxt][i], xb + i * 256u + ao);
#pragma unroll
                for (int q = 0; q < 4; q++) LDS128_F4(b[nxt][q], wb + bo + q * 256u);
            }
#pragma unroll
            for (int i = 0; i < 4; i++) {
                const float4 av = a[cur][i];
#pragma unroll
                for (int q = 0; q < 4; q++) {
                    const float4 bv = b[cur][q];
                    const float as = (q == 0) ? av.x : (q == 1) ? av.y : (q == 2) ? av.z : av.w;
                    acc[i][0] = fmaf(as, bv.x, acc[i][0]);
                    acc[i][1] = fmaf(as, bv.y, acc[i][1]);
                    acc[i][2] = fmaf(as, bv.z, acc[i][2]);
                    acc[i][3] = fmaf(as, bv.w, acc[i][3]);
                }
            }
        }
        __syncthreads();

        if (tid == 0 && c + 2 < NCHUNK) {
            MBAR_EXPECT_TX(sb + OFF_MBAR + s * 8, TX_BYTES);
            tma_2d(sb + OFF_X + s * X_STAGE, &tmx, (c + 2) * KC, tok0, sb + OFF_MBAR + s * 8);
            tma_2d(sb + OFF_W + s * W_STAGE, &tmw, 0, (c + 2) * KC, sb + OFF_MBAR + s * 8);
        }
    }

    // ---- epilogue: logits -> smem (alias x stages), per-token sigmoid+top-8 ----
    float* sc = (float*)(smem + OFF_X);   // [64 tok][68]
#pragma unroll
    for (int i = 0; i < 4; i++) {
        const int tok = tg * 4 + i;
        *(float4*)&sc[tok * 68 + eg * 4] =
            make_float4(acc[i][0], acc[i][1], acc[i][2], acc[i][3]);
    }
    __syncthreads();

    if (tid < TILE_M) {
        const long token = tok0 + tid;
        const float* gb = (const float*)(smem + OFF_GB);
        float s[NE];
#pragma unroll
        for (int e = 0; e < NE; e++)
            s[e] = 1.f / (1.f + expf(-sc[tid * 68 + e])) + gb[e];

        float* so = out + 2L * NT * TOPK + token * NE;
#pragma unroll
        for (int i = 0; i < 16; i++)
            *(float4*)&so[4 * i] = make_float4(s[4 * i], s[4 * i + 1], s[4 * i + 2], s[4 * i + 3]);

        // top-8, strict > keeps lowest index on ties (matches jax top_k)
        unsigned m0 = 0, m1 = 0;
        float wk[TOPK];
        int ik[TOPK];
        float sum = 0.f;
#pragma unroll 1
        for (int k = 0; k < TOPK; k++) {
            float best = -1e30f;
            int bi = 0;
#pragma unroll
            for (int e = 0; e < NE; e++) {
                unsigned bit = (e < 32) ? (m0 >> e) : (m1 >> (e - 32));
                if (((bit & 1u) == 0u) && (s[e] > best)) { best = s[e]; bi = e; }
            }
            if (bi < 32) m0 |= (1u << bi); else m1 |= (1u << (bi - 32));
            wk[k] = best; ik[k] = bi; sum += best;
        }
        // near-tie detection (incl. rank-8/9 boundary) -> flag for exact refine
        float v9 = -1e30f;
#pragma unroll
        for (int e = 0; e < NE; e++) {
            unsigned bit = (e < 32) ? (m0 >> e) : (m1 >> (e - 32));
            if (((bit & 1u) == 0u) && (s[e] > v9)) v9 = s[e];
        }
        float mingap = wk[TOPK - 1] - v9;
#pragma unroll
        for (int k = 0; k < TOPK - 1; k++) {
            float gdiff = wk[k] - wk[k + 1];
            if (gdiff < mingap) mingap = gdiff;
        }
        if (mingap < 2e-5f) {
            int ix = atomicAdd(&g_nflag, 1);
            if (ix < 8192) g_flags[ix] = (int)token;
        }

        float inv = 1.f / sum;
        *(float4*)&out[token * TOPK] = make_float4(wk[0] * inv, wk[1] * inv, wk[2] * inv, wk[3] * inv);
        *(float4*)&out[token * TOPK + 4] = make_float4(wk[4] * inv, wk[5] * inv, wk[6] * inv, wk[7] * inv);
        *(float4*)&out[NT * TOPK + token * TOPK] = make_float4((float)ik[0], (float)ik[1], (float)ik[2], (float)ik[3]);
        *(float4*)&out[NT * TOPK + token * TOPK + 4] = make_float4((float)ik[4], (float)ik[5], (float)ik[6], (float)ik[7]);
    }
}

// ---------------- refine: exact fp32 recompute for near-tie tokens ----------------
__global__ void refine_kernel(const float* __restrict__ x,
                              const float* __restrict__ w,
                              const float* __restrict__ gate_b,
                              float* __restrict__ out)
{
    __shared__ float xs[DIM];
    __shared__ float part[NE][4];
    __shared__ float sc[NE];
    int n = g_nflag;
    if (n > 8192) n = 8192;
    for (int i = blockIdx.x; i < n; i += gridDim.x) {
        const int token = g_flags[i];
        __syncthreads();
        for (int d = threadIdx.x; d < DIM; d += 256) xs[d] = x[(long)token * DIM + d];
        __syncthreads();
        {
            const int e = threadIdx.x >> 2, q = threadIdx.x & 3;
            const float* wr = w + (long)e * DIM + q * 512;
            const float* xr = xs + q * 512;
            float s0 = 0.f, s1 = 0.f, s2 = 0.f, s3 = 0.f;
#pragma unroll 8
            for (int d = 0; d < 512; d += 4) {
                s0 = fmaf(xr[d], wr[d], s0);
                s1 = fmaf(xr[d + 1], wr[d + 1], s1);
                s2 = fmaf(xr[d + 2], wr[d + 2], s2);
                s3 = fmaf(xr[d + 3], wr[d + 3], s3);
            }
            part[e][q] = (s0 + s1) + (s2 + s3);
        }
        __syncthreads();
        if (threadIdx.x < NE) {
            float l = (part[threadIdx.x][0] + part[threadIdx.x][1]) +
                      (part[threadIdx.x][2] + part[threadIdx.x][3]);
            float v = 1.f / (1.f + expf(-l)) + gate_b[threadIdx.x];
            sc[threadIdx.x] = v;
            out[2L * NT * TOPK + (long)token * NE + threadIdx.x] = v;
        }
        __syncthreads();
        if (threadIdx.x == 0) {
            unsigned m0 = 0, m1 = 0;
            float wk[TOPK];
            int ik[TOPK];
            float sum = 0.f;
            for (int k = 0; k < TOPK; k++) {
                float best = -1e30f;
                int bi = 0;
                for (int e = 0; e < NE; e++) {
                    unsigned bit = (e < 32) ? (m0 >> e) : (m1 >> (e - 32));
                    if (((bit & 1u) == 0u) && (sc[e] > best)) { best = sc[e]; bi = e; }
                }
                if (bi < 32) m0 |= (1u << bi); else m1 |= (1u << (bi - 32));
                wk[k] = best; ik[k] = bi; sum += best;
            }
            float inv = 1.f / sum;
            for (int k = 0; k < TOPK; k++) {
                out[(long)token * TOPK + k] = wk[k] * inv;
                out[NT * TOPK + (long)token * TOPK + k] = (float)ik[k];
            }
        }
    }
}

// ---------------- host ----------------
typedef CUresult (*EncodeFn)(CUtensorMap*, CUtensorMapDataType, cuuint32_t, void*,
                             const cuuint64_t*, const cuuint64_t*, const cuuint32_t*,
                             const cuuint32_t*, CUtensorMapInterleave, CUtensorMapSwizzle,
                             CUtensorMapL2promotion, CUtensorMapFloatOOBfill);

static EncodeFn get_encode_fn() {
    static EncodeFn fn = nullptr;
    if (!fn) {
        void* p = nullptr;
        cudaDriverEntryPointQueryResult qr;
        cudaGetDriverEntryPoint("cuTensorMapEncodeTiled", &p, cudaEnableDefault, &qr);
        fn = (EncodeFn)p;
    }
    return fn;
}

extern "C" void kernel_launch(void* const* d_in, const int* in_sizes, int n_in,
                              void* d_out, int out_size) {
    const float* x  = (const float*)d_in[0];
    const float* w  = (const float*)d_in[1];
    const float* gb = (const float*)d_in[2];
    float* out = (float*)d_out;

    prep_kernel<<<(DIM * NE) / 256, 256>>>(w);

    void* wtp = nullptr;
    cudaGetSymbolAddress(&wtp, g_wT);

    EncodeFn enc = get_encode_fn();
    CUtensorMap tmx, tmw;
    {
        cuuint64_t dims[2]    = {DIM, NT};
        cuuint64_t strides[1] = {DIM * sizeof(float)};
        cuuint32_t box[2]     = {KC, TILE_M};
        cuuint32_t es[2]      = {1, 1};
        enc(&tmx, CU_TENSOR_MAP_DATA_TYPE_FLOAT32, 2, (void*)x,
            dims, strides, box, es,
            CU_TENSOR_MAP_INTERLEAVE_NONE, CU_TENSOR_MAP_SWIZZLE_NONE,
            CU_TENSOR_MAP_L2_PROMOTION_L2_128B, CU_TENSOR_MAP_FLOAT_OOB_FILL_NONE);
    }
    {
        cuuint64_t dims[2]    = {NE, DIM};          // wT: inner = experts (256B rows)
        cuuint64_t strides[1] = {NE * sizeof(float)};
        cuuint32_t box[2]     = {NE, KC};
        cuuint32_t es[2]      = {1, 1};
        enc(&tmw, CU_TENSOR_MAP_DATA_TYPE_FLOAT32, 2, wtp,
            dims, strides, box, es,
            CU_TENSOR_MAP_INTERLEAVE_NONE, CU_TENSOR_MAP_SWIZZLE_NONE,
            CU_TENSOR_MAP_L2_PROMOTION_L2_128B, CU_TENSOR_MAP_FLOAT_OOB_FILL_NONE);
    }

    cudaFuncSetAttribute(gate_kernel, cudaFuncAttributeMaxDynamicSharedMemorySize, SMEM_TOTAL);
    gate_kernel<<<NT / TILE_M, THREADS, SMEM_TOTAL>>>(tmx, tmw, gb, out);
    refine_kernel<<<64, 256>>>(x, w, gb, out);
}